// round 15
// baseline (speedup 1.0000x reference)
#include <cuda_runtime.h>
#include <cuda_bf16.h>

#define NMAX 4096
#define BIGF 1e30f
#define TILE 128
#define NBLK 256
#define THREADS 256

// Scratch (__device__ globals; allocation is forbidden). All zero-init; the
// finalizer restores zeros each run -> replay-deterministic + first-call OK.
__device__ float4 g_rows[NMAX];        // compacted m1: (hx,hy,hz,-0.5*rr)
__device__ float4 g_cols[NMAX];        // compacted m2: (px,py,pz,-0.5*cc)
__device__ unsigned int g_e1[NMAX];    // ~bits(min D over m1 rows) per col; 0 == +inf
__device__ unsigned int g_e2[NMAX];    // ~bits(min D over m2 cols) per row; 0 == +inf
__device__ double g_sum1[64];          // telescoped sum of per-col mins
__device__ double g_sum2[64];          // telescoped sum of per-row mins
__device__ unsigned int g_done = 0;    // atomicInc(NBLK-1) self-wraps to 0

__device__ __forceinline__ double ldcg_d(const double* p) {
    double v;
    asm volatile("ld.global.cg.f64 %0, [%1];" : "=d"(v) : "l"(p) : "memory");
    return v;
}

// ---------------------------------------------------------------------------
// ONE kernel, NO grid barrier:
//  A) every block classifies all n points (identical deterministic scan) and
//     self-writes only the compacted windows its own tiles read.
//  B) tile math (unified): entries (x,y,z,w=-0.5|.|^2); u = dot + cw + rw;
//     D = -2u. Track M=max u per row/col; candidate v = clamp(-2M, 0, 1e30).
//  C) cross-block min via atomicMax on inverted bits; each improvement adds
//     the EXACT fp64 delta to spread slots -> Sum(final mins) with no re-read.
//  D) last arriving block sums 128 doubles, writes out, resets all state.
// ---------------------------------------------------------------------------
__global__ void __launch_bounds__(THREADS) fused_kernel(const float* __restrict__ norm,
                                                        const float* __restrict__ pts,
                                                        float* __restrict__ out,
                                                        int n) {
    __shared__ float4 srow[TILE];
    __shared__ float4 scol[TILE];
    __shared__ unsigned int credu[TILE];
    __shared__ unsigned int rredu[TILE];
    __shared__ int swtot[8];
    __shared__ int s_last;

    int t = threadIdx.x, lane = t & 31, w = t >> 5;
    if (n > NMAX) n = NMAX;

    float nx = __ldg(norm), ny = __ldg(norm + 1), nz = __ldg(norm + 2), dd = __ldg(norm + 3);
    float nn = nx * nx + ny * ny + nz * nz;

    // ---- A1: classify my 16 contiguous points ----
    unsigned mask = 0;
    int base_i = t * 16;
#pragma unroll
    for (int q = 0; q < 16; q++) {
        int i = base_i + q;
        if (i < n) {
            float px = __ldg(pts + 3 * i), py = __ldg(pts + 3 * i + 1), pz = __ldg(pts + 3 * i + 2);
            float ts = -2.f * (px * nx + py * ny + pz * nz + dd);
            if (ts > 0.f) mask |= 1u << q;
        }
    }
    int c1 = __popc(mask);
    int incv = c1;
#pragma unroll
    for (int o = 1; o < 32; o <<= 1) {
        int v = __shfl_up_sync(0xffffffffu, incv, o);
        if (lane >= o) incv += v;
    }
    if (lane == 31) swtot[w] = incv;
    __syncthreads();
    int wbase = 0, nr = 0;
#pragma unroll
    for (int k = 0; k < 8; k++) {
        int v = swtot[k];
        if (k < w) wbase += v;
        nr += v;
    }
    int P1 = wbase + incv - c1;   // m1 count before my chunk (deterministic, identical per block)
    int nc = n - nr;

    int ntr = (nr + TILE - 1) / TILE;
    int ntc = (nc + TILE - 1) / TILE;
    int ntiles = ntr * ntc;

    // my tiles (<=2 since ntiles <= 289) and their windows
    int t0 = blockIdx.x, t1 = blockIdx.x + NBLK;
    int rw0 = -1, cw0 = -1, rw1 = -1, cw1 = -1;
    if (t0 < ntiles) { int by = t0 / ntc, bx = t0 - by * ntc; rw0 = by; cw0 = bx; }
    if (t1 < ntiles) { int by = t1 / ntc, bx = t1 - by * ntc; rw1 = by; cw1 = bx; }

    // ---- A2: self-write only needed compacted entries (pts L1-hot reload) ----
    if (t0 < ntiles) {
        int run1 = P1;
#pragma unroll
        for (int q = 0; q < 16; q++) {
            int i = base_i + q;
            if (i >= n) break;
            bool m1 = (mask >> q) & 1u;
            int pos1 = run1;
            int pos2 = i - run1;
            if (m1) run1++;
            if (m1) {
                int wl = pos1 >> 7;
                if (wl == rw0 || wl == rw1) {
                    float px = __ldg(pts + 3 * i), py = __ldg(pts + 3 * i + 1), pz = __ldg(pts + 3 * i + 2);
                    float ts = -2.f * (px * nx + py * ny + pz * nz + dd);
                    float kk = ts / nn;
                    float hx = fmaf(kk, nx, px), hy = fmaf(kk, ny, py), hz = fmaf(kk, nz, pz);
                    float rr = fmaf(hx, hx, fmaf(hy, hy, hz * hz));
                    g_rows[pos1] = make_float4(hx, hy, hz, -0.5f * rr);
                }
            } else {
                int wl = pos2 >> 7;
                if (wl == cw0 || wl == cw1) {
                    float px = __ldg(pts + 3 * i), py = __ldg(pts + 3 * i + 1), pz = __ldg(pts + 3 * i + 2);
                    float cc = fmaf(px, px, fmaf(py, py, pz * pz));
                    g_cols[pos2] = make_float4(px, py, pz, -0.5f * cc);
                }
            }
        }
    }
    __syncthreads();   // own global writes visible block-wide (others write identical bytes)

    // ---- B+C: tiles ----
    int tx = t & 15, ty = t >> 4;
    int slot = blockIdx.x & 63;

    for (int tid = t0; tid < ntiles; tid += NBLK) {
        int by = tid / ntc, bx = tid - by * ntc;
        int i0 = by * TILE, j0 = bx * TILE;

        __syncthreads();
        if (t < TILE) {
            int gi = i0 + t;
            srow[t] = (gi < nr) ? g_rows[gi] : make_float4(0.f, 0.f, 0.f, -BIGF);
            credu[t] = 0u;
        } else {
            int u2 = t - TILE;
            int gj = j0 + u2;
            scol[u2] = (gj < nc) ? g_cols[gj] : make_float4(0.f, 0.f, 0.f, -BIGF);
            rredu[u2] = 0u;
        }
        __syncthreads();

        float RX[8], RY[8], RZ[8], RW[8];
#pragma unroll
        for (int r = 0; r < 8; r++) {
            float4 v = srow[ty * 8 + r];
            RX[r] = v.x; RY[r] = v.y; RZ[r] = v.z; RW[r] = v.w;
        }
        float CX[8], CY[8], CZ[8], CW[8];
#pragma unroll
        for (int c = 0; c < 8; c++) {
            float4 v = scol[c * 16 + tx];
            CX[c] = v.x; CY[c] = v.y; CZ[c] = v.z; CW[c] = v.w;
        }

        float Mr[8], Mc[8];
#pragma unroll
        for (int k = 0; k < 8; k++) { Mr[k] = -BIGF; Mc[k] = -BIGF; }

#pragma unroll
        for (int r = 0; r < 8; r++) {
            float rx = RX[r], ry = RY[r], rz = RZ[r], rw2 = RW[r];
            float mr = Mr[r];
#pragma unroll
            for (int c = 0; c < 8; c++) {
                float u1 = fmaf(rz, CZ[c], fmaf(ry, CY[c], fmaf(rx, CX[c], CW[c] + rw2)));
                mr    = fmaxf(mr, u1);
                Mc[c] = fmaxf(Mc[c], u1);
            }
            Mr[r] = mr;
        }

        // smem combine via inverted-bit atomicMax (identity 0)
#pragma unroll
        for (int c = 0; c < 8; c++) {
            float v = fminf(fmaxf(-2.f * Mc[c], 0.f), BIGF);
            atomicMax(&credu[c * 16 + tx], ~__float_as_uint(v));
        }
#pragma unroll
        for (int r = 0; r < 8; r++) {
            float v = fminf(fmaxf(-2.f * Mr[r], 0.f), BIGF);
            atomicMax(&rredu[ty * 8 + r], ~__float_as_uint(v));
        }
        __syncthreads();

        // global combine + exact fp64 telescoping delta
        if (t < TILE) {
            int gj = j0 + t;
            if (gj < nc) {
                unsigned e = credu[t];
                unsigned old = atomicMax(&g_e1[gj], e);
                if (e > old) {
                    double dv = (double)__uint_as_float(~e) -
                                (old ? (double)__uint_as_float(~old) : 0.0);
                    atomicAdd(&g_sum1[slot], dv);
                }
            }
        } else {
            int gi = i0 + (t - TILE);
            if (gi < nr) {
                unsigned e = rredu[t - TILE];
                unsigned old = atomicMax(&g_e2[gi], e);
                if (e > old) {
                    double dv = (double)__uint_as_float(~e) -
                                (old ? (double)__uint_as_float(~old) : 0.0);
                    atomicAdd(&g_sum2[slot], dv);
                }
            }
        }
    }

    // ---- D: last-arriving block finalizes (no barrier, no spin) ----
    __syncthreads();
    if (t == 0) {
        __threadfence();
        s_last = (atomicInc(&g_done, NBLK - 1) == NBLK - 1);
    }
    __syncthreads();
    if (!s_last) return;

    if (t == 0) {
        double S1 = 0.0, S2 = 0.0;
#pragma unroll 8
        for (int k = 0; k < 64; k++) {
            S1 += ldcg_d(&g_sum1[k]);
            S2 += ldcg_d(&g_sum2[k]);
        }
        double c2 = (nc > 0) ? (double)nc : 1.0;   // m2 count (av1 divisor)
        double c1d = (nr > 0) ? (double)nr : 1.0;  // m1 count (av2 divisor)
        out[0] = (float)((0.5 * (S1 / c2) + 0.5 * (S2 / c1d)) * 100.0);
    }
    __syncthreads();
    // restore zero-state for next replay
    for (int i = t; i < NMAX; i += THREADS) { g_e1[i] = 0u; g_e2[i] = 0u; }
    if (t < 64) { g_sum1[t] = 0.0; g_sum2[t] = 0.0; }
}

// ---------------------------------------------------------------------------
extern "C" void kernel_launch(void* const* d_in, const int* in_sizes, int n_in,
                              void* d_out, int out_size) {
    const float* a0 = (const float*)d_in[0];
    const float* a1 = (const float*)d_in[1];
    const float* norm;
    const float* pts;
    int n;
    if (in_sizes[0] == 4) { norm = a0; pts = a1; n = in_sizes[1] / 3; }
    else                  { norm = a1; pts = a0; n = in_sizes[0] / 3; }

    float* out = (float*)d_out;

    fused_kernel<<<NBLK, THREADS>>>(norm, pts, out, n);
}

// round 16
// speedup vs baseline: 1.9118x; 1.9118x over previous
#include <cuda_runtime.h>
#include <cuda_bf16.h>

#define NMAX 4096
#define BIGF 1e30f
#define TILE 128
#define DIST_BLOCKS 256
#define PREP_THREADS 256

// Scratch (__device__ globals; allocation is forbidden)
__device__ float4 g_rows[NMAX];        // compacted m1: (hx, hy, hz, rr)
__device__ float4 g_cols[NMAX];        // compacted m2: (px, py, pz, -0.5*cc)
__device__ unsigned int g_d1[NMAX];    // per m2-col slot: min over m1 rows (float bits)
__device__ unsigned int g_d2[NMAX];    // per m1-row slot: min over m2 cols (float bits)
__device__ int g_cnt[2] = {0, 0};      // {nr, nc}; reduce_kernel re-zeroes each replay

// ---------------------------------------------------------------------------
// Prep (multi-block): classify, compact via warp-aggregated GLOBAL atomics
// (slot order across blocks is nondeterministic — harmless: all consumers are
// order-invariant min/sum), init min arrays, bump counts.
// ---------------------------------------------------------------------------
__global__ void __launch_bounds__(PREP_THREADS) prep_kernel(const float* __restrict__ norm,
                                                            const float* __restrict__ pts,
                                                            int n) {
    int i = blockIdx.x * PREP_THREADS + threadIdx.x;
    int lane = threadIdx.x & 31;

    float nx = __ldg(norm), ny = __ldg(norm + 1), nz = __ldg(norm + 2), dd = __ldg(norm + 3);
    float nn = nx * nx + ny * ny + nz * nz;

    bool valid = i < n;
    float px = 0.f, py = 0.f, pz = 0.f, ts = 0.f;
    bool m1 = false;
    if (valid) {
        px = pts[3 * i]; py = pts[3 * i + 1]; pz = pts[3 * i + 2];
        ts = -2.0f * (px * nx + py * ny + pz * nz + dd);
        m1 = ts > 0.0f;
        g_d1[i] = __float_as_uint(BIGF);
        g_d2[i] = __float_as_uint(BIGF);
    }
    unsigned lanelt = (1u << lane) - 1u;

    unsigned mk1 = __ballot_sync(0xffffffffu, valid && m1);
    if (mk1) {
        int leader = __ffs(mk1) - 1;
        int base = 0;
        if (lane == leader) base = atomicAdd(&g_cnt[0], __popc(mk1));
        base = __shfl_sync(0xffffffffu, base, leader);
        if (valid && m1) {
            float kk = ts / nn;
            float hx = fmaf(kk, nx, px), hy = fmaf(kk, ny, py), hz = fmaf(kk, nz, pz);
            float rr = fmaf(hx, hx, fmaf(hy, hy, hz * hz));
            g_rows[base + __popc(mk1 & lanelt)] = make_float4(hx, hy, hz, rr);
        }
    }
    unsigned mk2 = __ballot_sync(0xffffffffu, valid && !m1);
    if (mk2) {
        int leader = __ffs(mk2) - 1;
        int base = 0;
        if (lane == leader) base = atomicAdd(&g_cnt[1], __popc(mk2));
        base = __shfl_sync(0xffffffffu, base, leader);
        if (valid && !m1) {
            float cc = fmaf(px, px, fmaf(py, py, pz * pz));
            g_cols[base + __popc(mk2 & lanelt)] = make_float4(px, py, pz, -0.5f * cc);
        }
    }
}

// ---------------------------------------------------------------------------
// Dist: persistent blocks over dynamic tile grid (nr x nc compacted).
// PDL consumer: grid-dependency-sync before reading prep's output.
//   u = dot(r,c) - 0.5cc; row min = rr - 2*max_c u; col min = min_r fma(u,-2,rr)
// ---------------------------------------------------------------------------
__global__ void __launch_bounds__(256) dist_kernel(int unused) {
#if __CUDA_ARCH__ >= 900
    cudaGridDependencySynchronize();   // wait for prep completion (PDL)
#endif
    __shared__ float4 srow[TILE];
    __shared__ float4 scol[TILE];
    __shared__ unsigned int credu[TILE];
    __shared__ unsigned int rredu[TILE];

    int t = threadIdx.x;
    int nr = g_cnt[0];
    int nc = g_cnt[1];
    int ntr = (nr + TILE - 1) / TILE;
    int ntc = (nc + TILE - 1) / TILE;
    int ntiles = ntr * ntc;
    int tx = t & 15, ty = t >> 4;

    for (int tile = blockIdx.x; tile < ntiles; tile += DIST_BLOCKS) {
        int by = tile / ntc;
        int bx = tile - by * ntc;
        int i0 = by * TILE;
        int j0 = bx * TILE;

        __syncthreads();                  // protect smem reuse across iterations
        if (t < TILE) {
            int gi = i0 + t;
            srow[t] = (gi < nr) ? g_rows[gi] : make_float4(0.f, 0.f, 0.f, BIGF);
            credu[t] = __float_as_uint(BIGF);
        } else {
            int u = t - TILE;
            int gj = j0 + u;
            scol[u] = (gj < nc) ? g_cols[gj] : make_float4(0.f, 0.f, 0.f, -BIGF);
            rredu[u] = __float_as_uint(BIGF);
        }
        __syncthreads();

        float RX[8], RY[8], RZ[8], RA[8];
#pragma unroll
        for (int r = 0; r < 8; r++) {
            float4 v = srow[ty * 8 + r];
            RX[r] = v.x; RY[r] = v.y; RZ[r] = v.z; RA[r] = v.w;   // rr (or BIG pad)
        }
        float CX[8], CY[8], CZ[8], CI[8];
#pragma unroll
        for (int c = 0; c < 8; c++) {
            float4 v = scol[c * 16 + tx];   // consecutive tx -> conflict-free
            CX[c] = v.x; CY[c] = v.y; CZ[c] = v.z; CI[c] = v.w;   // -0.5cc (or -BIG pad)
        }

        float cmin[8], umax[8];
#pragma unroll
        for (int k = 0; k < 8; k++) { cmin[k] = BIGF; umax[k] = -BIGF; }

#pragma unroll
        for (int r = 0; r < 8; r++) {
            float rxv = RX[r], ryv = RY[r], rzv = RZ[r], Av = RA[r];
            float um = umax[r];
#pragma unroll
            for (int c = 0; c < 8; c++) {
                float u = fmaf(rzv, CZ[c], fmaf(ryv, CY[c], fmaf(rxv, CX[c], CI[c])));
                um      = fmaxf(um, u);
                cmin[c] = fminf(cmin[c], fmaf(u, -2.0f, Av));
            }
            umax[r] = um;
        }

        // block-level combine (clamped >= 0 so uint order == float order)
#pragma unroll
        for (int c = 0; c < 8; c++)
            atomicMin(&credu[c * 16 + tx], __float_as_uint(fmaxf(cmin[c], 0.0f)));
#pragma unroll
        for (int r = 0; r < 8; r++) {
            float v = fmaxf(fmaf(umax[r], -2.0f, RA[r]), 0.0f);   // rr - 2*umax
            atomicMin(&rredu[ty * 8 + r], __float_as_uint(v));
        }
        __syncthreads();

        if (t < TILE) {
            int gj = j0 + t;
            if (gj < nc) atomicMin(&g_d1[gj], credu[t]);
        } else {
            int u = t - TILE;
            int gi = i0 + u;
            if (gi < nr) atomicMin(&g_d2[gi], rredu[u]);
        }
    }
}

// ---------------------------------------------------------------------------
// Reduce: PDL consumer; sums over compacted ranges; re-zeroes g_cnt.
// ---------------------------------------------------------------------------
__global__ void __launch_bounds__(1024) reduce_kernel(float* __restrict__ out) {
#if __CUDA_ARCH__ >= 900
    cudaGridDependencySynchronize();   // wait for dist completion (PDL)
#endif
    int t = threadIdx.x;
    int nr = g_cnt[0];
    int nc = g_cnt[1];
    int m = nr > nc ? nr : nc;
    float s1 = 0.f, s2 = 0.f;
    for (int i = t; i < m; i += 1024) {
        if (i < nc) s1 += __uint_as_float(g_d1[i]);
        if (i < nr) s2 += __uint_as_float(g_d2[i]);
    }
#pragma unroll
    for (int o = 16; o > 0; o >>= 1) {
        s1 += __shfl_xor_sync(0xffffffffu, s1, o);
        s2 += __shfl_xor_sync(0xffffffffu, s2, o);
    }
    __shared__ float sh[2][32];
    int w = t >> 5, l = t & 31;
    if (l == 0) { sh[0][w] = s1; sh[1][w] = s2; }
    __syncthreads();
    if (t == 0) { g_cnt[0] = 0; g_cnt[1] = 0; }   // restore pre-replay state
    if (w == 0) {
        float a = sh[0][l], b = sh[1][l];
#pragma unroll
        for (int o = 16; o > 0; o >>= 1) {
            a += __shfl_xor_sync(0xffffffffu, a, o);
            b += __shfl_xor_sync(0xffffffffu, b, o);
        }
        if (l == 0) {
            float c2 = fmaxf((float)nc, 1.0f);   // m2 count (av1 divisor)
            float c1 = fmaxf((float)nr, 1.0f);   // m1 count (av2 divisor)
            out[0] = (0.5f * (a / c2) + 0.5f * (b / c1)) * 100.0f;
        }
    }
}

// ---------------------------------------------------------------------------
extern "C" void kernel_launch(void* const* d_in, const int* in_sizes, int n_in,
                              void* d_out, int out_size) {
    const float* a0 = (const float*)d_in[0];
    const float* a1 = (const float*)d_in[1];
    const float* norm;
    const float* pts;
    int n;
    if (in_sizes[0] == 4) { norm = a0; pts = a1; n = in_sizes[1] / 3; }
    else                  { norm = a1; pts = a0; n = in_sizes[0] / 3; }

    float* out = (float*)d_out;

    int pb = (n + PREP_THREADS - 1) / PREP_THREADS;
    prep_kernel<<<pb, PREP_THREADS>>>(norm, pts, n);

    // PDL: overlap dependent-kernel launch prologue with predecessor execution
    cudaLaunchAttribute attr[1];
    attr[0].id = cudaLaunchAttributeProgrammaticStreamSerialization;
    attr[0].val.programmaticStreamSerializationAllowed = 1;

    cudaLaunchConfig_t cfg = {};
    cfg.stream = 0;
    cfg.attrs = attr;
    cfg.numAttrs = 1;

    cfg.gridDim = dim3(DIST_BLOCKS, 1, 1);
    cfg.blockDim = dim3(256, 1, 1);
    cudaLaunchKernelEx(&cfg, dist_kernel, 0);

    cfg.gridDim = dim3(1, 1, 1);
    cfg.blockDim = dim3(1024, 1, 1);
    cudaLaunchKernelEx(&cfg, reduce_kernel, out);
}

// round 17
// speedup vs baseline: 2.0312x; 1.0625x over previous
#include <cuda_runtime.h>
#include <cuda_bf16.h>

#define NMAX 4096
#define BIGF 1e30f
#define TILE 128
#define DIST_BLOCKS 256
#define PREP_THREADS 256

// Scratch (__device__ globals; allocation is forbidden)
__device__ float4 g_rows[NMAX];        // compacted m1: (hx, hy, hz, rr)
__device__ float4 g_cols[NMAX];        // compacted m2: (px, py, pz, -0.5*cc)
__device__ unsigned int g_d1[NMAX];    // per m2-col slot: min over m1 rows (float bits)
__device__ unsigned int g_d2[NMAX];    // per m1-row slot: min over m2 cols (float bits)
__device__ int g_cnt[2] = {0, 0};      // {nr, nc}; reduce_kernel re-zeroes each replay

// ---------------------------------------------------------------------------
// Prep: classify, compact via warp-aggregated global atomics, init mins.
// Triggers dependent (dist) launch IMMEDIATELY — consumer's
// cudaGridDependencySynchronize() still enforces the data dependency.
// ---------------------------------------------------------------------------
__global__ void __launch_bounds__(PREP_THREADS) prep_kernel(const float* __restrict__ norm,
                                                            const float* __restrict__ pts,
                                                            int n) {
#if __CUDA_ARCH__ >= 900
    if (threadIdx.x == 0) cudaTriggerProgrammaticLaunchCompletion();
#endif
    int i = blockIdx.x * PREP_THREADS + threadIdx.x;
    int lane = threadIdx.x & 31;

    float nx = __ldg(norm), ny = __ldg(norm + 1), nz = __ldg(norm + 2), dd = __ldg(norm + 3);
    float nn = nx * nx + ny * ny + nz * nz;

    bool valid = i < n;
    float px = 0.f, py = 0.f, pz = 0.f, ts = 0.f;
    bool m1 = false;
    if (valid) {
        px = pts[3 * i]; py = pts[3 * i + 1]; pz = pts[3 * i + 2];
        ts = -2.0f * (px * nx + py * ny + pz * nz + dd);
        m1 = ts > 0.0f;
        g_d1[i] = __float_as_uint(BIGF);
        g_d2[i] = __float_as_uint(BIGF);
    }
    unsigned lanelt = (1u << lane) - 1u;

    unsigned mk1 = __ballot_sync(0xffffffffu, valid && m1);
    if (mk1) {
        int leader = __ffs(mk1) - 1;
        int base = 0;
        if (lane == leader) base = atomicAdd(&g_cnt[0], __popc(mk1));
        base = __shfl_sync(0xffffffffu, base, leader);
        if (valid && m1) {
            float kk = ts / nn;
            float hx = fmaf(kk, nx, px), hy = fmaf(kk, ny, py), hz = fmaf(kk, nz, pz);
            float rr = fmaf(hx, hx, fmaf(hy, hy, hz * hz));
            g_rows[base + __popc(mk1 & lanelt)] = make_float4(hx, hy, hz, rr);
        }
    }
    unsigned mk2 = __ballot_sync(0xffffffffu, valid && !m1);
    if (mk2) {
        int leader = __ffs(mk2) - 1;
        int base = 0;
        if (lane == leader) base = atomicAdd(&g_cnt[1], __popc(mk2));
        base = __shfl_sync(0xffffffffu, base, leader);
        if (valid && !m1) {
            float cc = fmaf(px, px, fmaf(py, py, pz * pz));
            g_cols[base + __popc(mk2 & lanelt)] = make_float4(px, py, pz, -0.5f * cc);
        }
    }
}

// ---------------------------------------------------------------------------
// Dist: persistent blocks over dynamic tile grid (nr x nc compacted).
// PDL consumer AND producer: triggers reduce's launch immediately, then waits
// for prep's data before reading it.
// ---------------------------------------------------------------------------
__global__ void __launch_bounds__(256) dist_kernel(int unused) {
#if __CUDA_ARCH__ >= 900
    if (threadIdx.x == 0) cudaTriggerProgrammaticLaunchCompletion();
    cudaGridDependencySynchronize();   // wait for prep completion (PDL)
#endif
    __shared__ float4 srow[TILE];
    __shared__ float4 scol[TILE];
    __shared__ unsigned int credu[TILE];
    __shared__ unsigned int rredu[TILE];

    int t = threadIdx.x;
    int nr = g_cnt[0];
    int nc = g_cnt[1];
    int ntr = (nr + TILE - 1) / TILE;
    int ntc = (nc + TILE - 1) / TILE;
    int ntiles = ntr * ntc;
    int tx = t & 15, ty = t >> 4;

    for (int tile = blockIdx.x; tile < ntiles; tile += DIST_BLOCKS) {
        int by = tile / ntc;
        int bx = tile - by * ntc;
        int i0 = by * TILE;
        int j0 = bx * TILE;

        __syncthreads();                  // protect smem reuse across iterations
        if (t < TILE) {
            int gi = i0 + t;
            srow[t] = (gi < nr) ? g_rows[gi] : make_float4(0.f, 0.f, 0.f, BIGF);
            credu[t] = __float_as_uint(BIGF);
        } else {
            int u = t - TILE;
            int gj = j0 + u;
            scol[u] = (gj < nc) ? g_cols[gj] : make_float4(0.f, 0.f, 0.f, -BIGF);
            rredu[u] = __float_as_uint(BIGF);
        }
        __syncthreads();

        float RX[8], RY[8], RZ[8], RA[8];
#pragma unroll
        for (int r = 0; r < 8; r++) {
            float4 v = srow[ty * 8 + r];
            RX[r] = v.x; RY[r] = v.y; RZ[r] = v.z; RA[r] = v.w;   // rr (or BIG pad)
        }
        float CX[8], CY[8], CZ[8], CI[8];
#pragma unroll
        for (int c = 0; c < 8; c++) {
            float4 v = scol[c * 16 + tx];   // consecutive tx -> conflict-free
            CX[c] = v.x; CY[c] = v.y; CZ[c] = v.z; CI[c] = v.w;   // -0.5cc (or -BIG pad)
        }

        float cmin[8], umax[8];
#pragma unroll
        for (int k = 0; k < 8; k++) { cmin[k] = BIGF; umax[k] = -BIGF; }

#pragma unroll
        for (int r = 0; r < 8; r++) {
            float rxv = RX[r], ryv = RY[r], rzv = RZ[r], Av = RA[r];
            float um = umax[r];
#pragma unroll
            for (int c = 0; c < 8; c++) {
                float u = fmaf(rzv, CZ[c], fmaf(ryv, CY[c], fmaf(rxv, CX[c], CI[c])));
                um      = fmaxf(um, u);
                cmin[c] = fminf(cmin[c], fmaf(u, -2.0f, Av));
            }
            umax[r] = um;
        }

        // block-level combine (clamped >= 0 so uint order == float order)
#pragma unroll
        for (int c = 0; c < 8; c++)
            atomicMin(&credu[c * 16 + tx], __float_as_uint(fmaxf(cmin[c], 0.0f)));
#pragma unroll
        for (int r = 0; r < 8; r++) {
            float v = fmaxf(fmaf(umax[r], -2.0f, RA[r]), 0.0f);   // rr - 2*umax
            atomicMin(&rredu[ty * 8 + r], __float_as_uint(v));
        }
        __syncthreads();

        if (t < TILE) {
            int gj = j0 + t;
            if (gj < nc) atomicMin(&g_d1[gj], credu[t]);
        } else {
            int u = t - TILE;
            int gi = i0 + u;
            if (gi < nr) atomicMin(&g_d2[gi], rredu[u]);
        }
    }
}

// ---------------------------------------------------------------------------
// Reduce: PDL consumer; sums over compacted ranges; re-zeroes g_cnt.
// ---------------------------------------------------------------------------
__global__ void __launch_bounds__(1024) reduce_kernel(float* __restrict__ out) {
#if __CUDA_ARCH__ >= 900
    cudaGridDependencySynchronize();   // wait for dist completion (PDL)
#endif
    int t = threadIdx.x;
    int nr = g_cnt[0];
    int nc = g_cnt[1];
    int m = nr > nc ? nr : nc;
    float s1 = 0.f, s2 = 0.f;
    for (int i = t; i < m; i += 1024) {
        if (i < nc) s1 += __uint_as_float(g_d1[i]);
        if (i < nr) s2 += __uint_as_float(g_d2[i]);
    }
#pragma unroll
    for (int o = 16; o > 0; o >>= 1) {
        s1 += __shfl_xor_sync(0xffffffffu, s1, o);
        s2 += __shfl_xor_sync(0xffffffffu, s2, o);
    }
    __shared__ float sh[2][32];
    int w = t >> 5, l = t & 31;
    if (l == 0) { sh[0][w] = s1; sh[1][w] = s2; }
    __syncthreads();
    if (t == 0) { g_cnt[0] = 0; g_cnt[1] = 0; }   // restore pre-replay state
    if (w == 0) {
        float a = sh[0][l], b = sh[1][l];
#pragma unroll
        for (int o = 16; o > 0; o >>= 1) {
            a += __shfl_xor_sync(0xffffffffu, a, o);
            b += __shfl_xor_sync(0xffffffffu, b, o);
        }
        if (l == 0) {
            float c2 = fmaxf((float)nc, 1.0f);   // m2 count (av1 divisor)
            float c1 = fmaxf((float)nr, 1.0f);   // m1 count (av2 divisor)
            out[0] = (0.5f * (a / c2) + 0.5f * (b / c1)) * 100.0f;
        }
    }
}

// ---------------------------------------------------------------------------
extern "C" void kernel_launch(void* const* d_in, const int* in_sizes, int n_in,
                              void* d_out, int out_size) {
    const float* a0 = (const float*)d_in[0];
    const float* a1 = (const float*)d_in[1];
    const float* norm;
    const float* pts;
    int n;
    if (in_sizes[0] == 4) { norm = a0; pts = a1; n = in_sizes[1] / 3; }
    else                  { norm = a1; pts = a0; n = in_sizes[0] / 3; }

    float* out = (float*)d_out;

    // prep also launched with the PDL attribute so its own trigger is legal/no-op-safe
    cudaLaunchAttribute attr[1];
    attr[0].id = cudaLaunchAttributeProgrammaticStreamSerialization;
    attr[0].val.programmaticStreamSerializationAllowed = 1;

    cudaLaunchConfig_t cfg = {};
    cfg.stream = 0;
    cfg.attrs = nullptr;
    cfg.numAttrs = 0;

    int pb = (n + PREP_THREADS - 1) / PREP_THREADS;
    cfg.gridDim = dim3(pb, 1, 1);
    cfg.blockDim = dim3(PREP_THREADS, 1, 1);
    cudaLaunchKernelEx(&cfg, prep_kernel, norm, pts, n);

    cfg.attrs = attr;
    cfg.numAttrs = 1;

    cfg.gridDim = dim3(DIST_BLOCKS, 1, 1);
    cfg.blockDim = dim3(256, 1, 1);
    cudaLaunchKernelEx(&cfg, dist_kernel, 0);

    cfg.gridDim = dim3(1, 1, 1);
    cfg.blockDim = dim3(1024, 1, 1);
    cudaLaunchKernelEx(&cfg, reduce_kernel, out);
}